// round 14
// baseline (speedup 1.0000x reference)
#include <cuda_runtime.h>
#include <cuda_fp16.h>
#include <math.h>

#define EMB   1024
#define HID   2048
#define VOCAB 50257
#define T_STEPS 256
#define GH_BLOCKS 512
#define LOGIT_BLOCKS ((VOCAB + 15) / 16)   // 2 rows/warp * 8 warps (proven shape)
#define FUSED_BLOCKS (GH_BLOCKS + LOGIT_BLOCKS)
#define REFINE_BLOCKS 32
#define NKEYS (LOGIT_BLOCKS * 3)
#define KEY_CHUNK ((NKEYS + REFINE_BLOCKS - 1) / REFINE_BLOCKS)
#define STEP_BLOCKS (REFINE_BLOCKS + 512)

// Persistent state. h double-buffered; c in-place; g_key = packed argmax
// (orderable float bits << 32 | (0xFFFFFFFF - index)), double-buffered.
__device__ __align__(16) float g_h[2][HID];
__device__ __align__(16) float g_c[HID];
__device__ unsigned long long g_key[2];
__device__ unsigned int g_rdone[2];             // refine completion counters (parity)
__device__ __align__(16) float g_gh[4 * HID];   // h . W_hh partials (row-indexed)
__device__ unsigned long long g_btop[NKEYS];    // per-logits-block top-3 approx keys

// fp16 weight copies (scratch via __device__ globals, per harness rules).
__device__ __align__(16) __half g_wout_h[(size_t)VOCAB * HID];   // 206 MB
__device__ __align__(16) __half g_whh_h[(size_t)4 * HID * HID];  // 32 MB
__device__ __align__(16) __half g_wih_h[(size_t)4 * HID * EMB];  // 16 MB

__device__ __forceinline__ float sigmoidf_(float x) {
    return 1.0f / (1.0f + expf(-x));
}

__device__ __forceinline__ unsigned long long pack_key(float v, int idx) {
    unsigned ub = __float_as_uint(v);
    unsigned mk = (ub & 0x80000000u) ? ~ub : (ub | 0x80000000u);  // orderable float
    return ((unsigned long long)mk << 32) | (unsigned long long)(0xFFFFFFFFu - (unsigned)idx);
}

// fp16 uint4 (8 halves) dot 8 floats, fp32 accumulate.
__device__ __forceinline__ float dot8_h(uint4 wv, float4 ha, float4 hb) {
    float2 f0 = __half22float2(*(__half2*)&wv.x);
    float2 f1 = __half22float2(*(__half2*)&wv.y);
    float2 f2 = __half22float2(*(__half2*)&wv.z);
    float2 f3 = __half22float2(*(__half2*)&wv.w);
    return f0.x * ha.x + f0.y * ha.y + f1.x * ha.z + f1.y * ha.w
         + f2.x * hb.x + f2.y * hb.y + f3.x * hb.z + f3.y * hb.w;
}

__global__ void init_kernel() {
    int tid = blockIdx.x * blockDim.x + threadIdx.x;
    for (int i = tid; i < HID; i += 2048) {
        g_h[0][i] = 0.0f;
        g_h[1][i] = 0.0f;
        g_c[i]    = 0.0f;
    }
    for (int i = tid; i < 4 * HID; i += 2048) g_gh[i] = 0.0f;  // h0 = 0 -> gh = 0
    if (tid == 0) {
        g_key[0] = 0ull;
        g_key[1] = 0xFFFFFFFFull;  // decodes to token 0 for step 0
        g_rdone[0] = 0u;
        g_rdone[1] = 0u;
    }
}

// Generic fp32 -> fp16 convert: which = 0 (W_out), 1 (W_hh), 2 (W_ih).
// 16 elements (2 uint4) per thread; n16 = element count / 16.
__global__ void __launch_bounds__(256) convert_fp16_kernel(
    const float* __restrict__ src, int which, size_t n16)
{
    size_t i = (size_t)blockIdx.x * 256 + threadIdx.x;
    if (i >= n16) return;
    __half* dst = (which == 0) ? g_wout_h : (which == 1) ? g_whh_h : g_wih_h;
    const float4* p = (const float4*)src + 4 * i;
    uint4 o0, o1;
    {
        float4 a = __ldcs(p), b = __ldcs(p + 1);
        __half2 h0 = __floats2half2_rn(a.x, a.y);
        __half2 h1 = __floats2half2_rn(a.z, a.w);
        __half2 h2 = __floats2half2_rn(b.x, b.y);
        __half2 h3 = __floats2half2_rn(b.z, b.w);
        o0.x = *(unsigned*)&h0; o0.y = *(unsigned*)&h1;
        o0.z = *(unsigned*)&h2; o0.w = *(unsigned*)&h3;
    }
    {
        float4 a = __ldcs(p + 2), b = __ldcs(p + 3);
        __half2 h0 = __floats2half2_rn(a.x, a.y);
        __half2 h1 = __floats2half2_rn(a.z, a.w);
        __half2 h2 = __floats2half2_rn(b.x, b.y);
        __half2 h3 = __floats2half2_rn(b.z, b.w);
        o1.x = *(unsigned*)&h0; o1.y = *(unsigned*)&h1;
        o1.z = *(unsigned*)&h2; o1.w = *(unsigned*)&h3;
    }
    ((uint4*)dst)[2 * i]     = o0;
    ((uint4*)dst)[2 * i + 1] = o1;
}

// step_kernel(t): heterogeneous grid.
//   blocks [0, REFINE_BLOCKS): refine step t-1 — scan the 9426 per-block top-3
//     keys emitted by fused(t-1) (superset of the global top-3), exact fp32
//     recompute of the global top-3 rows, atomicMax exact key into
//     g_key[(t-1)&1], arrive on g_rdone[(t-1)&1].
//   blocks [REFINE_BLOCKS, STEP_BLOCKS): gates_x_cell(t) — PREFETCH the W_ih
//     tile (token-independent), then spin for the token, stage x, compute.
// Deadlock-safe: 544 blocks < one wave; refine blocks are lowest-indexed.
__global__ void __launch_bounds__(256) step_kernel(
    const float* __restrict__ emb,
    const float* __restrict__ W_out,
    const float* __restrict__ b_out,
    const float* __restrict__ b_ih,
    const float* __restrict__ b_hh,
    int t)
{
    const int tid  = threadIdx.x;
    const int lane = tid & 31;
    const int warp = tid >> 5;
    const int pt   = (t - 1) & 1;   // parity of the step being refined

    if (blockIdx.x < REFINE_BLOCKS) {
        // ---- refine part (step t-1): scan key superset, exact recompute ----
        __shared__ unsigned long long stop[8][3];
        __shared__ unsigned long long gtop[3];
        __shared__ unsigned long long res[3];

        if (t > 0) {
            const int kbeg = blockIdx.x * KEY_CHUNK;
            const int kend = min(kbeg + KEY_CHUNK, NKEYS);

            unsigned long long k0 = 0, k1 = 0, k2 = 0;
            for (int v = kbeg + tid; v < kend; v += 256) {
                unsigned long long key = __ldcg(&g_btop[v]);
                if (key > k0)      { k2 = k1; k1 = k0; k0 = key; }
                else if (key > k1) { k2 = k1; k1 = key; }
                else if (key > k2) { k2 = key; }
            }
            #pragma unroll
            for (int r = 0; r < 3; r++) {
                unsigned long long m = k0;
                #pragma unroll
                for (int off = 16; off > 0; off >>= 1) {
                    unsigned long long o = __shfl_xor_sync(0xFFFFFFFFu, m, off);
                    if (o > m) m = o;
                }
                if (k0 == m) { k0 = k1; k1 = k2; k2 = 0; }
                if (lane == 0) stop[warp][r] = m;
            }
            __syncthreads();
            if (warp == 0) {
                k0 = (lane < 8) ? stop[lane][0] : 0;
                k1 = (lane < 8) ? stop[lane][1] : 0;
                k2 = (lane < 8) ? stop[lane][2] : 0;
                #pragma unroll
                for (int r = 0; r < 3; r++) {
                    unsigned long long m = k0;
                    #pragma unroll
                    for (int off = 16; off > 0; off >>= 1) {
                        unsigned long long o = __shfl_xor_sync(0xFFFFFFFFu, m, off);
                        if (o > m) m = o;
                    }
                    if (k0 == m) { k0 = k1; k1 = k2; k2 = 0; }
                    if (lane == 0) gtop[r] = m;
                }
            }
            __syncthreads();

            // Exact fp32 recompute for the 3 candidates; h(t) = g_h[t&1].
            if (warp < 3) {
                unsigned long long key = gtop[warp];
                int v = (int)(0xFFFFFFFFu - (unsigned)(key & 0xFFFFFFFFull));
                const float4* w  = (const float4*)(W_out + (size_t)v * HID);
                const float4* h4 = (const float4*)(g_h[t & 1]);
                float acc = 0.f;
                #pragma unroll
                for (int it = 0; it < 16; it++) {
                    int idx = it * 32 + lane;
                    float4 wv = __ldg(&w[idx]);
                    float4 hv = __ldg(&h4[idx]);
                    acc += wv.x * hv.x + wv.y * hv.y + wv.z * hv.z + wv.w * hv.w;
                }
                #pragma unroll
                for (int off = 16; off > 0; off >>= 1)
                    acc += __shfl_xor_sync(0xFFFFFFFFu, acc, off);
                if (lane == 0) res[warp] = pack_key(acc + __ldg(&b_out[v]), v);
            }
            __syncthreads();
            if (tid == 0) {
                unsigned long long best = res[0];
                if (res[1] > best) best = res[1];
                if (res[2] > best) best = res[2];
                atomicMax(&g_key[pt], best);
            }
        }
        if (tid == 0) {
            __threadfence();
            atomicAdd(&g_rdone[pt], 1u);    // arrive (t==0: counter-only)
        }
        return;
    }

    // ---- gates_x_cell part (step t) ----
    __shared__ __align__(16) float sx[EMB];
    __shared__ float spart[8][4];
    __shared__ int stok;

    const int bx   = blockIdx.x - REFINE_BLOCKS;
    const int jl   = warp >> 1;
    const int half = warp & 1;
    const int j    = bx * 4 + jl;
    const int base = half * (EMB / 2);              // element offset (512)

    // Prefetch the W_ih tile (token-independent) BEFORE the refine spin:
    // the 8 loads fly while we wait for the token.
    const uint4* wi0 = (const uint4*)(g_wih_h + (size_t)(j          ) * EMB + base);
    const uint4* wi1 = (const uint4*)(g_wih_h + (size_t)(j +     HID) * EMB + base);
    const uint4* wi2 = (const uint4*)(g_wih_h + (size_t)(j + 2 * HID) * EMB + base);
    const uint4* wi3 = (const uint4*)(g_wih_h + (size_t)(j + 3 * HID) * EMB + base);
    uint4 w00 = __ldg(&wi0[lane]);
    uint4 w01 = __ldg(&wi0[32 + lane]);
    uint4 w10 = __ldg(&wi1[lane]);
    uint4 w11 = __ldg(&wi1[32 + lane]);
    uint4 w20 = __ldg(&wi2[lane]);
    uint4 w21 = __ldg(&wi2[32 + lane]);
    uint4 w30 = __ldg(&wi3[lane]);
    uint4 w31 = __ldg(&wi3[32 + lane]);

    if (tid == 0) {
        while (atomicAdd(&g_rdone[pt], 0u) < (unsigned)REFINE_BLOCKS)
            __nanosleep(64);
        unsigned long long key = atomicAdd(&g_key[pt], 0ull);
        stok = (int)(0xFFFFFFFFu - (unsigned)(key & 0xFFFFFFFFull));
    }
    __syncthreads();
    const int tok = stok;
    if (bx == 0 && tid == 0) g_key[t & 1] = 0ull;   // refine(t) accumulates here

    const float4* xe = (const float4*)(emb + (size_t)tok * EMB);
    ((float4*)sx)[tid] = xe[tid];
    __syncthreads();

    float a0, a1, a2, a3;
    {
        float4 xa0 = *(const float4*)(sx + base + lane * 8);
        float4 xb0 = *(const float4*)(sx + base + lane * 8 + 4);
        float4 xa1 = *(const float4*)(sx + base + 256 + lane * 8);
        float4 xb1 = *(const float4*)(sx + base + 256 + lane * 8 + 4);
        a0 = dot8_h(w00, xa0, xb0) + dot8_h(w01, xa1, xb1);
        a1 = dot8_h(w10, xa0, xb0) + dot8_h(w11, xa1, xb1);
        a2 = dot8_h(w20, xa0, xb0) + dot8_h(w21, xa1, xb1);
        a3 = dot8_h(w30, xa0, xb0) + dot8_h(w31, xa1, xb1);
    }

    #pragma unroll
    for (int off = 16; off > 0; off >>= 1) {
        a0 += __shfl_xor_sync(0xFFFFFFFFu, a0, off);
        a1 += __shfl_xor_sync(0xFFFFFFFFu, a1, off);
        a2 += __shfl_xor_sync(0xFFFFFFFFu, a2, off);
        a3 += __shfl_xor_sync(0xFFFFFFFFu, a3, off);
    }
    if (lane == 0) {
        spart[warp][0] = a0; spart[warp][1] = a1;
        spart[warp][2] = a2; spart[warp][3] = a3;
    }
    __syncthreads();

    if (tid < 4) {
        const int jj = bx * 4 + tid;
        const int w0 = 2 * tid;
        float s0 = spart[w0][0] + spart[w0 + 1][0] + g_gh[jj          ]
                 + b_ih[jj          ] + b_hh[jj          ];
        float s1 = spart[w0][1] + spart[w0 + 1][1] + g_gh[jj +     HID]
                 + b_ih[jj +     HID] + b_hh[jj +     HID];
        float s2 = spart[w0][2] + spart[w0 + 1][2] + g_gh[jj + 2 * HID]
                 + b_ih[jj + 2 * HID] + b_hh[jj + 2 * HID];
        float s3 = spart[w0][3] + spart[w0 + 1][3] + g_gh[jj + 3 * HID]
                 + b_ih[jj + 3 * HID] + b_hh[jj + 3 * HID];
        float ig = sigmoidf_(s0);
        float fg = sigmoidf_(s1);
        float gg = tanhf(s2);
        float og = sigmoidf_(s3);
        float c  = fg * g_c[jj] + ig * gg;
        g_c[jj] = c;
        g_h[(t + 1) & 1][jj] = og * tanhf(c);
    }
}

// Fused kernel (hot loops unchanged): blocks [0, GH_BLOCKS) compute gh =
// h(t+1) . W_hh; blocks [GH_BLOCKS, FUSED_BLOCKS) compute this step's fp16
// logits (2 rows/warp) AND emit the block-local top-3 approx keys to g_btop.
// Also resets g_rdone[t&1] for the refine(t) inside step_kernel(t+1).
__global__ void __launch_bounds__(256, 6) fused_logits_gh_kernel(
    const float* __restrict__ b_out,
    float* __restrict__ out,
    int t)
{
    __shared__ __align__(16) float sh[HID];
    __shared__ float spart[8][4];
    __shared__ unsigned long long skey[16];

    const int tid  = threadIdx.x;
    const int lane = tid & 31;
    const int warp = tid >> 5;

    if (blockIdx.x == 0 && tid == 0) g_rdone[t & 1] = 0u;

    const float4* h4 = (const float4*)(g_h[(t + 1) & 1]);
    ((float4*)sh)[tid]       = h4[tid];
    ((float4*)sh)[tid + 256] = h4[tid + 256];
    __syncthreads();

    const float4* sh4 = (const float4*)sh;

    if (blockIdx.x < GH_BLOCKS) {
        // ---- gh part: 4 j per block, split-K x2, fp16 uint4 __ldg ----
        const int jl   = warp >> 1;
        const int half = warp & 1;
        const int j    = blockIdx.x * 4 + jl;
        const int base = half * (HID / 2);          // element offset (1024)

        float a0 = 0.f, a1 = 0.f, a2 = 0.f, a3 = 0.f;
        const uint4* wh0 = (const uint4*)(g_whh_h + (size_t)(j          ) * HID + base);
        const uint4* wh1 = (const uint4*)(g_whh_h + (size_t)(j +     HID) * HID + base);
        const uint4* wh2 = (const uint4*)(g_whh_h + (size_t)(j + 2 * HID) * HID + base);
        const uint4* wh3 = (const uint4*)(g_whh_h + (size_t)(j + 3 * HID) * HID + base);
        #pragma unroll
        for (int it = 0; it < 4; it++) {            // 1024 halves / (32*8) = 4
            int idx = it * 32 + lane;
            float4 ha = *(const float4*)(sh + base + idx * 8);
            float4 hb = *(const float4*)(sh + base + idx * 8 + 4);
            a0 += dot8_h(__ldg(&wh0[idx]), ha, hb);
            a1 += dot8_h(__ldg(&wh1[idx]), ha, hb);
            a2 += dot8_h(__ldg(&wh2[idx]), ha, hb);
            a3 += dot8_h(__ldg(&wh3[idx]), ha, hb);
        }

        #pragma unroll
        for (int off = 16; off > 0; off >>= 1) {
            a0 += __shfl_xor_sync(0xFFFFFFFFu, a0, off);
            a1 += __shfl_xor_sync(0xFFFFFFFFu, a1, off);
            a2 += __shfl_xor_sync(0xFFFFFFFFu, a2, off);
            a3 += __shfl_xor_sync(0xFFFFFFFFu, a3, off);
        }
        if (lane == 0) {
            spart[warp][0] = a0; spart[warp][1] = a1;
            spart[warp][2] = a2; spart[warp][3] = a3;
        }
        __syncthreads();

        if (tid < 4) {
            const int jj = blockIdx.x * 4 + tid;
            const int w0 = 2 * tid;
            g_gh[jj          ] = spart[w0][0] + spart[w0 + 1][0];
            g_gh[jj +     HID] = spart[w0][1] + spart[w0 + 1][1];
            g_gh[jj + 2 * HID] = spart[w0][2] + spart[w0 + 1][2];
            g_gh[jj + 3 * HID] = spart[w0][3] + spart[w0 + 1][3];
        }
        return;
    }

    // ---- logits part: 2 rows/warp, uint4 __ldcs streaming loads ----
    const int lb = blockIdx.x - GH_BLOCKS;
    const int v0 = lb * 16 + warp * 2;
    const int v1 = v0 + 1;
    const bool p0 = v0 < VOCAB;
    const bool p1 = v1 < VOCAB;

    const uint4* w0 = (const uint4*)(g_wout_h + (size_t)v0 * HID);
    const uint4* w1 = (const uint4*)(g_wout_h + (size_t)v1 * HID);

    float acc0 = 0.f, acc1 = 0.f;
    #pragma unroll
    for (int it = 0; it < 8; it++) {                // 2048 halves / (32 lanes * 8) = 8
        int idx = it * 32 + lane;
        float4 ha = sh4[2 * idx];
        float4 hb = sh4[2 * idx + 1];
        if (p0) acc0 += dot8_h(__ldcs(&w0[idx]), ha, hb);
        if (p1) acc1 += dot8_h(__ldcs(&w1[idx]), ha, hb);
    }
    #pragma unroll
    for (int off = 16; off > 0; off >>= 1) {
        acc0 += __shfl_xor_sync(0xFFFFFFFFu, acc0, off);
        acc1 += __shfl_xor_sync(0xFFFFFFFFu, acc1, off);
    }
    if (lane == 0) {
        unsigned long long k0 = 0ull, k1 = 0ull;
        if (p0) {
            float l0 = acc0 + __ldg(&b_out[v0]);
            __stcs(&out[(size_t)t * VOCAB + v0], l0);
            k0 = pack_key(l0, v0);
        }
        if (p1) {
            float l1 = acc1 + __ldg(&b_out[v1]);
            __stcs(&out[(size_t)t * VOCAB + v1], l1);
            k1 = pack_key(l1, v1);
        }
        skey[warp * 2]     = k0;
        skey[warp * 2 + 1] = k1;
    }
    __syncthreads();

    // Block-local top-3 of the 16 keys -> g_btop (superset of global top-3).
    if (warp == 0) {
        unsigned long long k = (lane < 16) ? skey[lane] : 0ull;
        #pragma unroll
        for (int r = 0; r < 3; r++) {
            unsigned long long m = k;
            #pragma unroll
            for (int off = 16; off > 0; off >>= 1) {
                unsigned long long o = __shfl_xor_sync(0xFFFFFFFFu, m, off);
                if (o > m) m = o;
            }
            if (k == m) k = 0ull;
            if (lane == 0) g_btop[lb * 3 + r] = m;
        }
    }
}

extern "C" void kernel_launch(void* const* d_in, const int* in_sizes, int n_in,
                              void* d_out, int out_size)
{
    const float* emb   = (const float*)d_in[0];
    const float* W_ih  = (const float*)d_in[1];
    const float* W_hh  = (const float*)d_in[2];
    const float* b_ih  = (const float*)d_in[3];
    const float* b_hh  = (const float*)d_in[4];
    const float* W_out = (const float*)d_in[5];
    const float* b_out = (const float*)d_in[6];
    float* out = (float*)d_out;

    init_kernel<<<2, 1024>>>();
    {
        size_t n16;
        n16 = (size_t)VOCAB * HID / 16;
        convert_fp16_kernel<<<(unsigned)((n16 + 255) / 256), 256>>>(W_out, 0, n16);
        n16 = (size_t)4 * HID * HID / 16;
        convert_fp16_kernel<<<(unsigned)((n16 + 255) / 256), 256>>>(W_hh, 1, n16);
        n16 = (size_t)4 * HID * EMB / 16;
        convert_fp16_kernel<<<(unsigned)((n16 + 255) / 256), 256>>>(W_ih, 2, n16);
    }

    for (int t = 0; t < T_STEPS; t++) {
        step_kernel<<<STEP_BLOCKS, 256>>>(emb, W_out, b_out, b_ih, b_hh, t);
        fused_logits_gh_kernel<<<FUSED_BLOCKS, 256>>>(b_out, out, t);
    }
}

// round 15
// speedup vs baseline: 1.2719x; 1.2719x over previous
#include <cuda_runtime.h>
#include <cuda_fp16.h>
#include <math.h>

#define EMB   1024
#define HID   2048
#define VOCAB 50257
#define T_STEPS 256
#define GH_BLOCKS 512
#define LOGIT_BLOCKS ((VOCAB + 15) / 16)   // 2 rows/warp * 8 warps (proven shape)
#define FUSED_BLOCKS (GH_BLOCKS + LOGIT_BLOCKS)
#define REFINE_BLOCKS 32
#define REFINE_CHUNK ((VOCAB + REFINE_BLOCKS - 1) / REFINE_BLOCKS)
#define STEP_BLOCKS (REFINE_BLOCKS + 512)

// Persistent state. h double-buffered; c in-place; g_key = packed argmax
// (orderable float bits << 32 | (0xFFFFFFFF - index)), double-buffered.
__device__ __align__(16) float g_h[2][HID];
__device__ __align__(16) float g_c[HID];
__device__ unsigned long long g_key[2];
__device__ unsigned int g_rdone[2];             // refine completion counters (parity)
__device__ __align__(16) float g_gh[4 * HID];   // h . W_hh partials (row-indexed)

// fp16 weight copies (scratch via __device__ globals, per harness rules).
__device__ __align__(16) __half g_wout_h[(size_t)VOCAB * HID];   // 206 MB
__device__ __align__(16) __half g_whh_h[(size_t)4 * HID * HID];  // 32 MB
__device__ __align__(16) __half g_wih_h[(size_t)4 * HID * EMB];  // 16 MB

__device__ __forceinline__ float sigmoidf_(float x) {
    return 1.0f / (1.0f + expf(-x));
}

__device__ __forceinline__ unsigned long long pack_key(float v, int idx) {
    unsigned ub = __float_as_uint(v);
    unsigned mk = (ub & 0x80000000u) ? ~ub : (ub | 0x80000000u);  // orderable float
    return ((unsigned long long)mk << 32) | (unsigned long long)(0xFFFFFFFFu - (unsigned)idx);
}

// fp16 uint4 (8 halves) dot 8 floats, fp32 accumulate.
__device__ __forceinline__ float dot8_h(uint4 wv, float4 ha, float4 hb) {
    float2 f0 = __half22float2(*(__half2*)&wv.x);
    float2 f1 = __half22float2(*(__half2*)&wv.y);
    float2 f2 = __half22float2(*(__half2*)&wv.z);
    float2 f3 = __half22float2(*(__half2*)&wv.w);
    return f0.x * ha.x + f0.y * ha.y + f1.x * ha.z + f1.y * ha.w
         + f2.x * hb.x + f2.y * hb.y + f3.x * hb.z + f3.y * hb.w;
}

__global__ void init_kernel() {
    int tid = blockIdx.x * blockDim.x + threadIdx.x;
    for (int i = tid; i < HID; i += 2048) {
        g_h[0][i] = 0.0f;
        g_h[1][i] = 0.0f;
        g_c[i]    = 0.0f;
    }
    for (int i = tid; i < 4 * HID; i += 2048) g_gh[i] = 0.0f;  // h0 = 0 -> gh = 0
    if (tid == 0) {
        g_key[0] = 0ull;
        g_key[1] = 0xFFFFFFFFull;  // decodes to token 0 for step 0
        g_rdone[0] = 0u;
        g_rdone[1] = 0u;
    }
}

// Generic fp32 -> fp16 convert: which = 0 (W_out), 1 (W_hh), 2 (W_ih).
// 16 elements (2 uint4) per thread; n16 = element count / 16.
__global__ void __launch_bounds__(256) convert_fp16_kernel(
    const float* __restrict__ src, int which, size_t n16)
{
    size_t i = (size_t)blockIdx.x * 256 + threadIdx.x;
    if (i >= n16) return;
    __half* dst = (which == 0) ? g_wout_h : (which == 1) ? g_whh_h : g_wih_h;
    const float4* p = (const float4*)src + 4 * i;
    uint4 o0, o1;
    {
        float4 a = __ldcs(p), b = __ldcs(p + 1);
        __half2 h0 = __floats2half2_rn(a.x, a.y);
        __half2 h1 = __floats2half2_rn(a.z, a.w);
        __half2 h2 = __floats2half2_rn(b.x, b.y);
        __half2 h3 = __floats2half2_rn(b.z, b.w);
        o0.x = *(unsigned*)&h0; o0.y = *(unsigned*)&h1;
        o0.z = *(unsigned*)&h2; o0.w = *(unsigned*)&h3;
    }
    {
        float4 a = __ldcs(p + 2), b = __ldcs(p + 3);
        __half2 h0 = __floats2half2_rn(a.x, a.y);
        __half2 h1 = __floats2half2_rn(a.z, a.w);
        __half2 h2 = __floats2half2_rn(b.x, b.y);
        __half2 h3 = __floats2half2_rn(b.z, b.w);
        o1.x = *(unsigned*)&h0; o1.y = *(unsigned*)&h1;
        o1.z = *(unsigned*)&h2; o1.w = *(unsigned*)&h3;
    }
    ((uint4*)dst)[2 * i]     = o0;
    ((uint4*)dst)[2 * i + 1] = o1;
}

// step_kernel(t): heterogeneous grid (exact R12 code).
//   blocks [0, REFINE_BLOCKS): refine step t-1 — slice-local approx-top-3 over
//     logits(t-1), exact fp32 recompute of those rows, atomicMax of the exact
//     packed key into g_key[(t-1)&1], then arrive on g_rdone[(t-1)&1].
//   blocks [REFINE_BLOCKS, STEP_BLOCKS): gates_x_cell for step t — spin until
//     all refine blocks arrived, read the token, then x.W_ih + gh + biases ->
//     nonlinearities -> h(t+1), c.
// Deadlock-safe: 544 blocks < one wave; refine blocks are lowest-indexed.
__global__ void __launch_bounds__(256) step_kernel(
    const float* __restrict__ emb,
    const float* __restrict__ W_out,
    const float* __restrict__ b_out,
    const float* __restrict__ b_ih,
    const float* __restrict__ b_hh,
    const float* __restrict__ out,
    int t)
{
    const int tid  = threadIdx.x;
    const int lane = tid & 31;
    const int warp = tid >> 5;
    const int pt   = (t - 1) & 1;   // parity of the step being refined

    if (blockIdx.x < REFINE_BLOCKS) {
        // ---- refine part (step t-1) ----
        __shared__ unsigned long long stop[8][3];
        __shared__ unsigned long long gtop[3];
        __shared__ unsigned long long res[3];

        if (t > 0) {
            const float* lg = out + (size_t)(t - 1) * VOCAB;
            const int vbeg = blockIdx.x * REFINE_CHUNK;
            const int vend = min(vbeg + REFINE_CHUNK, VOCAB);

            unsigned long long k0 = 0, k1 = 0, k2 = 0;
            for (int v = vbeg + tid; v < vend; v += 256) {
                unsigned long long key = pack_key(__ldcg(&lg[v]), v);
                if (key > k0)      { k2 = k1; k1 = k0; k0 = key; }
                else if (key > k1) { k2 = k1; k1 = key; }
                else if (key > k2) { k2 = key; }
            }
            #pragma unroll
            for (int r = 0; r < 3; r++) {
                unsigned long long m = k0;
                #pragma unroll
                for (int off = 16; off > 0; off >>= 1) {
                    unsigned long long o = __shfl_xor_sync(0xFFFFFFFFu, m, off);
                    if (o > m) m = o;
                }
                if (k0 == m) { k0 = k1; k1 = k2; k2 = 0; }
                if (lane == 0) stop[warp][r] = m;
            }
            __syncthreads();
            if (warp == 0) {
                k0 = (lane < 8) ? stop[lane][0] : 0;
                k1 = (lane < 8) ? stop[lane][1] : 0;
                k2 = (lane < 8) ? stop[lane][2] : 0;
                #pragma unroll
                for (int r = 0; r < 3; r++) {
                    unsigned long long m = k0;
                    #pragma unroll
                    for (int off = 16; off > 0; off >>= 1) {
                        unsigned long long o = __shfl_xor_sync(0xFFFFFFFFu, m, off);
                        if (o > m) m = o;
                    }
                    if (k0 == m) { k0 = k1; k1 = k2; k2 = 0; }
                    if (lane == 0) gtop[r] = m;
                }
            }
            __syncthreads();

            // Exact fp32 recompute for the 3 candidates; h(t) = g_h[t&1].
            if (warp < 3) {
                unsigned long long key = gtop[warp];
                int v = (int)(0xFFFFFFFFu - (unsigned)(key & 0xFFFFFFFFull));
                const float4* w  = (const float4*)(W_out + (size_t)v * HID);
                const float4* h4 = (const float4*)(g_h[t & 1]);
                float acc = 0.f;
                #pragma unroll
                for (int it = 0; it < 16; it++) {
                    int idx = it * 32 + lane;
                    float4 wv = __ldg(&w[idx]);
                    float4 hv = __ldg(&h4[idx]);
                    acc += wv.x * hv.x + wv.y * hv.y + wv.z * hv.z + wv.w * hv.w;
                }
                #pragma unroll
                for (int off = 16; off > 0; off >>= 1)
                    acc += __shfl_xor_sync(0xFFFFFFFFu, acc, off);
                if (lane == 0) res[warp] = pack_key(acc + __ldg(&b_out[v]), v);
            }
            __syncthreads();
            if (tid == 0) {
                unsigned long long best = res[0];
                if (res[1] > best) best = res[1];
                if (res[2] > best) best = res[2];
                atomicMax(&g_key[pt], best);
            }
        }
        if (tid == 0) {
            __threadfence();
            atomicAdd(&g_rdone[pt], 1u);    // arrive (t==0: counter-only)
        }
        return;
    }

    // ---- gates_x_cell part (step t) ----
    __shared__ __align__(16) float sx[EMB];
    __shared__ float spart[8][4];
    __shared__ int stok;

    if (tid == 0) {
        while (atomicAdd(&g_rdone[pt], 0u) < (unsigned)REFINE_BLOCKS)
            __nanosleep(64);
        unsigned long long key = atomicAdd(&g_key[pt], 0ull);
        stok = (int)(0xFFFFFFFFu - (unsigned)(key & 0xFFFFFFFFull));
    }
    __syncthreads();
    const int tok = stok;
    const int bx  = blockIdx.x - REFINE_BLOCKS;
    if (bx == 0 && tid == 0) g_key[t & 1] = 0ull;   // refine(t) accumulates here

    const float4* xe = (const float4*)(emb + (size_t)tok * EMB);
    ((float4*)sx)[tid] = xe[tid];
    __syncthreads();

    const int jl   = warp >> 1;
    const int half = warp & 1;
    const int j    = bx * 4 + jl;
    const int base = half * (EMB / 2);              // element offset (512)

    float a0 = 0.f, a1 = 0.f, a2 = 0.f, a3 = 0.f;
    const uint4* wi0 = (const uint4*)(g_wih_h + (size_t)(j          ) * EMB + base);
    const uint4* wi1 = (const uint4*)(g_wih_h + (size_t)(j +     HID) * EMB + base);
    const uint4* wi2 = (const uint4*)(g_wih_h + (size_t)(j + 2 * HID) * EMB + base);
    const uint4* wi3 = (const uint4*)(g_wih_h + (size_t)(j + 3 * HID) * EMB + base);
    #pragma unroll
    for (int it = 0; it < 2; it++) {                // 512 halves / (32*8) = 2
        int idx = it * 32 + lane;
        float4 xa = *(const float4*)(sx + base + idx * 8);
        float4 xb = *(const float4*)(sx + base + idx * 8 + 4);
        a0 += dot8_h(__ldg(&wi0[idx]), xa, xb);
        a1 += dot8_h(__ldg(&wi1[idx]), xa, xb);
        a2 += dot8_h(__ldg(&wi2[idx]), xa, xb);
        a3 += dot8_h(__ldg(&wi3[idx]), xa, xb);
    }

    #pragma unroll
    for (int off = 16; off > 0; off >>= 1) {
        a0 += __shfl_xor_sync(0xFFFFFFFFu, a0, off);
        a1 += __shfl_xor_sync(0xFFFFFFFFu, a1, off);
        a2 += __shfl_xor_sync(0xFFFFFFFFu, a2, off);
        a3 += __shfl_xor_sync(0xFFFFFFFFu, a3, off);
    }
    if (lane == 0) {
        spart[warp][0] = a0; spart[warp][1] = a1;
        spart[warp][2] = a2; spart[warp][3] = a3;
    }
    __syncthreads();

    if (tid < 4) {
        const int jj = bx * 4 + tid;
        const int w0 = 2 * tid;
        float s0 = spart[w0][0] + spart[w0 + 1][0] + g_gh[jj          ]
                 + b_ih[jj          ] + b_hh[jj          ];
        float s1 = spart[w0][1] + spart[w0 + 1][1] + g_gh[jj +     HID]
                 + b_ih[jj +     HID] + b_hh[jj +     HID];
        float s2 = spart[w0][2] + spart[w0 + 1][2] + g_gh[jj + 2 * HID]
                 + b_ih[jj + 2 * HID] + b_hh[jj + 2 * HID];
        float s3 = spart[w0][3] + spart[w0 + 1][3] + g_gh[jj + 3 * HID]
                 + b_ih[jj + 3 * HID] + b_hh[jj + 3 * HID];
        float ig = sigmoidf_(s0);
        float fg = sigmoidf_(s1);
        float gg = tanhf(s2);
        float og = sigmoidf_(s3);
        float c  = fg * g_c[jj] + ig * gg;
        g_c[jj] = c;
        g_h[(t + 1) & 1][jj] = og * tanhf(c);
    }
}

// Fused kernel (R12 branch bodies, roles REORDERED): blocks [0, LOGIT_BLOCKS)
// compute this step's fp16 logits (the 206 MB critical stream starts first);
// blocks [LOGIT_BLOCKS, FUSED_BLOCKS) compute gh = h(t+1) . W_hh (only needed
// by step_kernel(t+1), so scheduling it last is free). Resets g_rdone[t&1].
__global__ void __launch_bounds__(256, 6) fused_logits_gh_kernel(
    const float* __restrict__ b_out,
    float* __restrict__ out,
    int t)
{
    __shared__ __align__(16) float sh[HID];
    __shared__ float spart[8][4];

    const int tid  = threadIdx.x;
    const int lane = tid & 31;
    const int warp = tid >> 5;

    if (blockIdx.x == 0 && tid == 0) g_rdone[t & 1] = 0u;

    const float4* h4 = (const float4*)(g_h[(t + 1) & 1]);
    ((float4*)sh)[tid]       = h4[tid];
    ((float4*)sh)[tid + 256] = h4[tid + 256];
    __syncthreads();

    const float4* sh4 = (const float4*)sh;

    if (blockIdx.x >= LOGIT_BLOCKS) {
        // ---- gh part: 4 j per block, split-K x2, fp16 uint4 __ldg ----
        const int gb   = blockIdx.x - LOGIT_BLOCKS;
        const int jl   = warp >> 1;
        const int half = warp & 1;
        const int j    = gb * 4 + jl;
        const int base = half * (HID / 2);          // element offset (1024)

        float a0 = 0.f, a1 = 0.f, a2 = 0.f, a3 = 0.f;
        const uint4* wh0 = (const uint4*)(g_whh_h + (size_t)(j          ) * HID + base);
        const uint4* wh1 = (const uint4*)(g_whh_h + (size_t)(j +     HID) * HID + base);
        const uint4* wh2 = (const uint4*)(g_whh_h + (size_t)(j + 2 * HID) * HID + base);
        const uint4* wh3 = (const uint4*)(g_whh_h + (size_t)(j + 3 * HID) * HID + base);
        #pragma unroll
        for (int it = 0; it < 4; it++) {            // 1024 halves / (32*8) = 4
            int idx = it * 32 + lane;
            float4 ha = *(const float4*)(sh + base + idx * 8);
            float4 hb = *(const float4*)(sh + base + idx * 8 + 4);
            a0 += dot8_h(__ldg(&wh0[idx]), ha, hb);
            a1 += dot8_h(__ldg(&wh1[idx]), ha, hb);
            a2 += dot8_h(__ldg(&wh2[idx]), ha, hb);
            a3 += dot8_h(__ldg(&wh3[idx]), ha, hb);
        }

        #pragma unroll
        for (int off = 16; off > 0; off >>= 1) {
            a0 += __shfl_xor_sync(0xFFFFFFFFu, a0, off);
            a1 += __shfl_xor_sync(0xFFFFFFFFu, a1, off);
            a2 += __shfl_xor_sync(0xFFFFFFFFu, a2, off);
            a3 += __shfl_xor_sync(0xFFFFFFFFu, a3, off);
        }
        if (lane == 0) {
            spart[warp][0] = a0; spart[warp][1] = a1;
            spart[warp][2] = a2; spart[warp][3] = a3;
        }
        __syncthreads();

        if (tid < 4) {
            const int jj = gb * 4 + tid;
            const int w0 = 2 * tid;
            g_gh[jj          ] = spart[w0][0] + spart[w0 + 1][0];
            g_gh[jj +     HID] = spart[w0][1] + spart[w0 + 1][1];
            g_gh[jj + 2 * HID] = spart[w0][2] + spart[w0 + 1][2];
            g_gh[jj + 3 * HID] = spart[w0][3] + spart[w0 + 1][3];
        }
        return;
    }

    // ---- logits part: 2 rows/warp, uint4 __ldcs streaming loads ----
    const int lb = blockIdx.x;
    const int v0 = lb * 16 + warp * 2;
    const int v1 = v0 + 1;
    const bool p0 = v0 < VOCAB;
    const bool p1 = v1 < VOCAB;

    const uint4* w0 = (const uint4*)(g_wout_h + (size_t)v0 * HID);
    const uint4* w1 = (const uint4*)(g_wout_h + (size_t)v1 * HID);

    float acc0 = 0.f, acc1 = 0.f;
    #pragma unroll
    for (int it = 0; it < 8; it++) {                // 2048 halves / (32 lanes * 8) = 8
        int idx = it * 32 + lane;
        float4 ha = sh4[2 * idx];
        float4 hb = sh4[2 * idx + 1];
        if (p0) acc0 += dot8_h(__ldcs(&w0[idx]), ha, hb);
        if (p1) acc1 += dot8_h(__ldcs(&w1[idx]), ha, hb);
    }
    #pragma unroll
    for (int off = 16; off > 0; off >>= 1) {
        acc0 += __shfl_xor_sync(0xFFFFFFFFu, acc0, off);
        acc1 += __shfl_xor_sync(0xFFFFFFFFu, acc1, off);
    }
    if (lane == 0 && p0) __stcs(&out[(size_t)t * VOCAB + v0], acc0 + __ldg(&b_out[v0]));
    if (lane == 0 && p1) __stcs(&out[(size_t)t * VOCAB + v1], acc1 + __ldg(&b_out[v1]));
}

extern "C" void kernel_launch(void* const* d_in, const int* in_sizes, int n_in,
                              void* d_out, int out_size)
{
    const float* emb   = (const float*)d_in[0];
    const float* W_ih  = (const float*)d_in[1];
    const float* W_hh  = (const float*)d_in[2];
    const float* b_ih  = (const float*)d_in[3];
    const float* b_hh  = (const float*)d_in[4];
    const float* W_out = (const float*)d_in[5];
    const float* b_out = (const float*)d_in[6];
    float* out = (float*)d_out;

    init_kernel<<<2, 1024>>>();
    {
        size_t n16;
        n16 = (size_t)VOCAB * HID / 16;
        convert_fp16_kernel<<<(unsigned)((n16 + 255) / 256), 256>>>(W_out, 0, n16);
        n16 = (size_t)4 * HID * HID / 16;
        convert_fp16_kernel<<<(unsigned)((n16 + 255) / 256), 256>>>(W_hh, 1, n16);
        n16 = (size_t)4 * HID * EMB / 16;
        convert_fp16_kernel<<<(unsigned)((n16 + 255) / 256), 256>>>(W_ih, 2, n16);
    }

    for (int t = 0; t < T_STEPS; t++) {
        step_kernel<<<STEP_BLOCKS, 256>>>(emb, W_out, b_out, b_ih, b_hh, out, t);
        fused_logits_gh_kernel<<<FUSED_BLOCKS, 256>>>(b_out, out, t);
    }
}

// round 17
// speedup vs baseline: 1.2765x; 1.0036x over previous
#include <cuda_runtime.h>
#include <cuda_fp16.h>
#include <math.h>

#define EMB   1024
#define HID   2048
#define VOCAB 50257
#define T_STEPS 256
#define GH_BLOCKS 512
#define LOGIT_BLOCKS ((VOCAB + 15) / 16)   // 2 rows/warp * 8 warps (proven shape)
#define FUSED_BLOCKS (GH_BLOCKS + LOGIT_BLOCKS)
#define REFINE_BLOCKS 32
#define REFINE_CHUNK ((VOCAB + REFINE_BLOCKS - 1) / REFINE_BLOCKS)
#define STEP_BLOCKS (REFINE_BLOCKS + 512)

// Convert-kernel geometry (one fused preamble grid).
#define N16_WOUT ((size_t)VOCAB * HID / 16)            // 6,432,896 -> 25129 blocks
#define N16_WHH  ((size_t)4 * HID * HID / 16)          // 1,048,576 ->  4096 blocks
#define N16_WIH  ((size_t)4 * HID * EMB / 16)          //   524,288 ->  2048 blocks
#define CB_WOUT  ((unsigned)((N16_WOUT + 255) / 256))
#define CB_WHH   ((unsigned)((N16_WHH  + 255) / 256))
#define CB_WIH   ((unsigned)((N16_WIH  + 255) / 256))
#define PRE_BLOCKS (CB_WOUT + CB_WHH + CB_WIH + 1)     // +1 init block

// Persistent state. h double-buffered; c in-place; g_key = packed argmax
// (orderable float bits << 32 | (0xFFFFFFFF - index)), double-buffered.
__device__ __align__(16) float g_h[2][HID];
__device__ __align__(16) float g_c[HID];
__device__ unsigned long long g_key[2];
__device__ unsigned int g_rdone[2];             // refine completion counters (parity)
__device__ __align__(16) float g_gh[4 * HID];   // h . W_hh partials (row-indexed)

// fp16 weight copies (scratch via __device__ globals, per harness rules).
__device__ __align__(16) __half g_wout_h[(size_t)VOCAB * HID];   // 206 MB
__device__ __align__(16) __half g_whh_h[(size_t)4 * HID * HID];  // 32 MB
__device__ __align__(16) __half g_wih_h[(size_t)4 * HID * EMB];  // 16 MB

__device__ __forceinline__ float sigmoidf_(float x) {
    return 1.0f / (1.0f + expf(-x));
}

__device__ __forceinline__ unsigned long long pack_key(float v, int idx) {
    unsigned ub = __float_as_uint(v);
    unsigned mk = (ub & 0x80000000u) ? ~ub : (ub | 0x80000000u);  // orderable float
    return ((unsigned long long)mk << 32) | (unsigned long long)(0xFFFFFFFFu - (unsigned)idx);
}

// fp16 uint4 (8 halves) dot 8 floats, fp32 accumulate.
__device__ __forceinline__ float dot8_h(uint4 wv, float4 ha, float4 hb) {
    float2 f0 = __half22float2(*(__half2*)&wv.x);
    float2 f1 = __half22float2(*(__half2*)&wv.y);
    float2 f2 = __half22float2(*(__half2*)&wv.z);
    float2 f3 = __half22float2(*(__half2*)&wv.w);
    return f0.x * ha.x + f0.y * ha.y + f1.x * ha.z + f1.y * ha.w
         + f2.x * hb.x + f2.y * hb.y + f3.x * hb.z + f3.y * hb.w;
}

__device__ __forceinline__ void cvt16(const float* __restrict__ src, __half* dst, size_t i) {
    const float4* p = (const float4*)src + 4 * i;
    uint4 o0, o1;
    {
        float4 a = __ldcs(p), b = __ldcs(p + 1);
        __half2 h0 = __floats2half2_rn(a.x, a.y);
        __half2 h1 = __floats2half2_rn(a.z, a.w);
        __half2 h2 = __floats2half2_rn(b.x, b.y);
        __half2 h3 = __floats2half2_rn(b.z, b.w);
        o0.x = *(unsigned*)&h0; o0.y = *(unsigned*)&h1;
        o0.z = *(unsigned*)&h2; o0.w = *(unsigned*)&h3;
    }
    {
        float4 a = __ldcs(p + 2), b = __ldcs(p + 3);
        __half2 h0 = __floats2half2_rn(a.x, a.y);
        __half2 h1 = __floats2half2_rn(a.z, a.w);
        __half2 h2 = __floats2half2_rn(b.x, b.y);
        __half2 h3 = __floats2half2_rn(b.z, b.w);
        o1.x = *(unsigned*)&h0; o1.y = *(unsigned*)&h1;
        o1.z = *(unsigned*)&h2; o1.w = *(unsigned*)&h3;
    }
    ((uint4*)dst)[2 * i]     = o0;
    ((uint4*)dst)[2 * i + 1] = o1;
}

// Preamble: one grid does state init + all three fp32->fp16 converts.
// Role by block range: [0, CB_WOUT) W_out, [CB_WOUT, +CB_WHH) W_hh,
// [+, +CB_WIH) W_ih, last block = state init.
__global__ void __launch_bounds__(256) preamble_kernel(
    const float* __restrict__ W_out,
    const float* __restrict__ W_hh,
    const float* __restrict__ W_ih)
{
    const unsigned bx = blockIdx.x;
    const int tid = threadIdx.x;
    if (bx < CB_WOUT) {
        size_t i = (size_t)bx * 256 + tid;
        if (i < N16_WOUT) cvt16(W_out, g_wout_h, i);
        return;
    }
    if (bx < CB_WOUT + CB_WHH) {
        size_t i = (size_t)(bx - CB_WOUT) * 256 + tid;
        if (i < N16_WHH) cvt16(W_hh, g_whh_h, i);
        return;
    }
    if (bx < CB_WOUT + CB_WHH + CB_WIH) {
        size_t i = (size_t)(bx - CB_WOUT - CB_WHH) * 256 + tid;
        if (i < N16_WIH) cvt16(W_ih, g_wih_h, i);
        return;
    }
    // state init block
    for (int i = tid; i < HID; i += 256) {
        g_h[0][i] = 0.0f;
        g_h[1][i] = 0.0f;
        g_c[i]    = 0.0f;
    }
    for (int i = tid; i < 4 * HID; i += 256) g_gh[i] = 0.0f;  // h0 = 0 -> gh = 0
    if (tid == 0) {
        g_key[0] = 0ull;
        g_key[1] = 0xFFFFFFFFull;  // decodes to token 0 for step 0
        g_rdone[0] = 0u;
        g_rdone[1] = 0u;
    }
}

// step_kernel(t): heterogeneous grid (R12/R15 code).
//   blocks [0, REFINE_BLOCKS): refine step t-1 — slice-local approx-top-3 over
//     logits(t-1) (L2-resident now), exact fp32 recompute of those rows,
//     atomicMax exact key into g_key[(t-1)&1], arrive on g_rdone[(t-1)&1].
//   blocks [REFINE_BLOCKS, STEP_BLOCKS): gates_x_cell for step t — spin until
//     all refine blocks arrived, read the token, then x.W_ih + gh + biases ->
//     nonlinearities -> h(t+1), c.
// Deadlock-safe: 544 blocks < one wave; refine blocks are lowest-indexed.
__global__ void __launch_bounds__(256) step_kernel(
    const float* __restrict__ emb,
    const float* __restrict__ W_out,
    const float* __restrict__ b_out,
    const float* __restrict__ b_ih,
    const float* __restrict__ b_hh,
    const float* __restrict__ out,
    int t)
{
    const int tid  = threadIdx.x;
    const int lane = tid & 31;
    const int warp = tid >> 5;
    const int pt   = (t - 1) & 1;   // parity of the step being refined

    if (blockIdx.x < REFINE_BLOCKS) {
        // ---- refine part (step t-1) ----
        __shared__ unsigned long long stop[8][3];
        __shared__ unsigned long long gtop[3];
        __shared__ unsigned long long res[3];

        if (t > 0) {
            const float* lg = out + (size_t)(t - 1) * VOCAB;
            const int vbeg = blockIdx.x * REFINE_CHUNK;
            const int vend = min(vbeg + REFINE_CHUNK, VOCAB);

            unsigned long long k0 = 0, k1 = 0, k2 = 0;
            for (int v = vbeg + tid; v < vend; v += 256) {
                unsigned long long key = pack_key(__ldcg(&lg[v]), v);
                if (key > k0)      { k2 = k1; k1 = k0; k0 = key; }
                else if (key > k1) { k2 = k1; k1 = key; }
                else if (key > k2) { k2 = key; }
            }
            #pragma unroll
            for (int r = 0; r < 3; r++) {
                unsigned long long m = k0;
                #pragma unroll
                for (int off = 16; off > 0; off >>= 1) {
                    unsigned long long o = __shfl_xor_sync(0xFFFFFFFFu, m, off);
                    if (o > m) m = o;
                }
                if (k0 == m) { k0 = k1; k1 = k2; k2 = 0; }
                if (lane == 0) stop[warp][r] = m;
            }
            __syncthreads();
            if (warp == 0) {
                k0 = (lane < 8) ? stop[lane][0] : 0;
                k1 = (lane < 8) ? stop[lane][1] : 0;
                k2 = (lane < 8) ? stop[lane][2] : 0;
                #pragma unroll
                for (int r = 0; r < 3; r++) {
                    unsigned long long m = k0;
                    #pragma unroll
                    for (int off = 16; off > 0; off >>= 1) {
                        unsigned long long o = __shfl_xor_sync(0xFFFFFFFFu, m, off);
                        if (o > m) m = o;
                    }
                    if (k0 == m) { k0 = k1; k1 = k2; k2 = 0; }
                    if (lane == 0) gtop[r] = m;
                }
            }
            __syncthreads();

            // Exact fp32 recompute for the 3 candidates; h(t) = g_h[t&1].
            if (warp < 3) {
                unsigned long long key = gtop[warp];
                int v = (int)(0xFFFFFFFFu - (unsigned)(key & 0xFFFFFFFFull));
                const float4* w  = (const float4*)(W_out + (size_t)v * HID);
                const float4* h4 = (const float4*)(g_h[t & 1]);
                float acc = 0.f;
                #pragma unroll
                for (int it = 0; it < 16; it++) {
                    int idx = it * 32 + lane;
                    float4 wv = __ldg(&w[idx]);
                    float4 hv = __ldg(&h4[idx]);
                    acc += wv.x * hv.x + wv.y * hv.y + wv.z * hv.z + wv.w * hv.w;
                }
                #pragma unroll
                for (int off = 16; off > 0; off >>= 1)
                    acc += __shfl_xor_sync(0xFFFFFFFFu, acc, off);
                if (lane == 0) res[warp] = pack_key(acc + __ldg(&b_out[v]), v);
            }
            __syncthreads();
            if (tid == 0) {
                unsigned long long best = res[0];
                if (res[1] > best) best = res[1];
                if (res[2] > best) best = res[2];
                atomicMax(&g_key[pt], best);
            }
        }
        if (tid == 0) {
            __threadfence();
            atomicAdd(&g_rdone[pt], 1u);    // arrive (t==0: counter-only)
        }
        return;
    }

    // ---- gates_x_cell part (step t) ----
    __shared__ __align__(16) float sx[EMB];
    __shared__ float spart[8][4];
    __shared__ int stok;

    if (tid == 0) {
        while (atomicAdd(&g_rdone[pt], 0u) < (unsigned)REFINE_BLOCKS)
            __nanosleep(64);
        unsigned long long key = atomicAdd(&g_key[pt], 0ull);
        stok = (int)(0xFFFFFFFFu - (unsigned)(key & 0xFFFFFFFFull));
    }
    __syncthreads();
    const int tok = stok;
    const int bx  = blockIdx.x - REFINE_BLOCKS;
    if (bx == 0 && tid == 0) g_key[t & 1] = 0ull;   // refine(t) accumulates here

    const float4* xe = (const float4*)(emb + (size_t)tok * EMB);
    ((float4*)sx)[tid] = xe[tid];
    __syncthreads();

    const int jl   = warp >> 1;
    const int half = warp & 1;
    const int j    = bx * 4 + jl;
    const int base = half * (EMB / 2);              // element offset (512)

    float a0 = 0.f, a1 = 0.f, a2 = 0.f, a3 = 0.f;
    const uint4* wi0 = (const uint4*)(g_wih_h + (size_t)(j          ) * EMB + base);
    const uint4* wi1 = (const uint4*)(g_wih_h + (size_t)(j +     HID) * EMB + base);
    const uint4* wi2 = (const uint4*)(g_wih_h + (size_t)(j + 2 * HID) * EMB + base);
    const uint4* wi3 = (const uint4*)(g_wih_h + (size_t)(j + 3 * HID) * EMB + base);
    #pragma unroll
    for (int it = 0; it < 2; it++) {                // 512 halves / (32*8) = 2
        int idx = it * 32 + lane;
        float4 xa = *(const float4*)(sx + base + idx * 8);
        float4 xb = *(const float4*)(sx + base + idx * 8 + 4);
        a0 += dot8_h(__ldg(&wi0[idx]), xa, xb);
        a1 += dot8_h(__ldg(&wi1[idx]), xa, xb);
        a2 += dot8_h(__ldg(&wi2[idx]), xa, xb);
        a3 += dot8_h(__ldg(&wi3[idx]), xa, xb);
    }

    #pragma unroll
    for (int off = 16; off > 0; off >>= 1) {
        a0 += __shfl_xor_sync(0xFFFFFFFFu, a0, off);
        a1 += __shfl_xor_sync(0xFFFFFFFFu, a1, off);
        a2 += __shfl_xor_sync(0xFFFFFFFFu, a2, off);
        a3 += __shfl_xor_sync(0xFFFFFFFFu, a3, off);
    }
    if (lane == 0) {
        spart[warp][0] = a0; spart[warp][1] = a1;
        spart[warp][2] = a2; spart[warp][3] = a3;
    }
    __syncthreads();

    if (tid < 4) {
        const int jj = bx * 4 + tid;
        const int w0 = 2 * tid;
        float s0 = spart[w0][0] + spart[w0 + 1][0] + g_gh[jj          ]
                 + b_ih[jj          ] + b_hh[jj          ];
        float s1 = spart[w0][1] + spart[w0 + 1][1] + g_gh[jj +     HID]
                 + b_ih[jj +     HID] + b_hh[jj +     HID];
        float s2 = spart[w0][2] + spart[w0 + 1][2] + g_gh[jj + 2 * HID]
                 + b_ih[jj + 2 * HID] + b_hh[jj + 2 * HID];
        float s3 = spart[w0][3] + spart[w0 + 1][3] + g_gh[jj + 3 * HID]
                 + b_ih[jj + 3 * HID] + b_hh[jj + 3 * HID];
        float ig = sigmoidf_(s0);
        float fg = sigmoidf_(s1);
        float gg = tanhf(s2);
        float og = sigmoidf_(s3);
        float c  = fg * g_c[jj] + ig * gg;
        g_c[jj] = c;
        g_h[(t + 1) & 1][jj] = og * tanhf(c);
    }
}

// Fused kernel (R15 layout): blocks [0, LOGIT_BLOCKS) compute this step's fp16
// logits (critical stream scheduled first); blocks [LOGIT_BLOCKS, FUSED_BLOCKS)
// compute gh = h(t+1) . W_hh. Logits stores are now plain (L2-resident for
// next step's refine scan). Resets g_rdone[t&1].
__global__ void __launch_bounds__(256, 6) fused_logits_gh_kernel(
    const float* __restrict__ b_out,
    float* __restrict__ out,
    int t)
{
    __shared__ __align__(16) float sh[HID];
    __shared__ float spart[8][4];

    const int tid  = threadIdx.x;
    const int lane = tid & 31;
    const int warp = tid >> 5;

    if (blockIdx.x == 0 && tid == 0) g_rdone[t & 1] = 0u;

    const float4* h4 = (const float4*)(g_h[(t + 1) & 1]);
    ((float4*)sh)[tid]       = h4[tid];
    ((float4*)sh)[tid + 256] = h4[tid + 256];
    __syncthreads();

    const float4* sh4 = (const float4*)sh;

    if (blockIdx.x >= LOGIT_BLOCKS) {
        // ---- gh part: 4 j per block, split-K x2, fp16 uint4 __ldg ----
        const int gb   = blockIdx.x - LOGIT_BLOCKS;
        const int jl   = warp >> 1;
        const int half = warp & 1;
        const int j    = gb * 4 + jl;
        const int base = half * (HID / 2);          // element offset (1024)

        float a0 = 0.f, a1 = 0.f, a2 = 0.f, a3 = 0.f;
        const uint4* wh0 = (const uint4*)(g_whh_h + (size_t)(j          ) * HID + base);
        const uint4* wh1 = (const uint4*)(g_whh_h + (size_t)(j +     HID) * HID + base);
        const uint4* wh2 = (const uint4*)(g_whh_h + (size_t)(j + 2 * HID) * HID + base);
        const uint4* wh3 = (const uint4*)(g_whh_h + (size_t)(j + 3 * HID) * HID + base);
        #pragma unroll
        for (int it = 0; it < 4; it++) {            // 1024 halves / (32*8) = 4
            int idx = it * 32 + lane;
            float4 ha = *(const float4*)(sh + base + idx * 8);
            float4 hb = *(const float4*)(sh + base + idx * 8 + 4);
            a0 += dot8_h(__ldg(&wh0[idx]), ha, hb);
            a1 += dot8_h(__ldg(&wh1[idx]), ha, hb);
            a2 += dot8_h(__ldg(&wh2[idx]), ha, hb);
            a3 += dot8_h(__ldg(&wh3[idx]), ha, hb);
        }

        #pragma unroll
        for (int off = 16; off > 0; off >>= 1) {
            a0 += __shfl_xor_sync(0xFFFFFFFFu, a0, off);
            a1 += __shfl_xor_sync(0xFFFFFFFFu, a1, off);
            a2 += __shfl_xor_sync(0xFFFFFFFFu, a2, off);
            a3 += __shfl_xor_sync(0xFFFFFFFFu, a3, off);
        }
        if (lane == 0) {
            spart[warp][0] = a0; spart[warp][1] = a1;
            spart[warp][2] = a2; spart[warp][3] = a3;
        }
        __syncthreads();

        if (tid < 4) {
            const int jj = gb * 4 + tid;
            const int w0 = 2 * tid;
            g_gh[jj          ] = spart[w0][0] + spart[w0 + 1][0];
            g_gh[jj +     HID] = spart[w0][1] + spart[w0 + 1][1];
            g_gh[jj + 2 * HID] = spart[w0][2] + spart[w0 + 1][2];
            g_gh[jj + 3 * HID] = spart[w0][3] + spart[w0 + 1][3];
        }
        return;
    }

    // ---- logits part: 2 rows/warp, uint4 __ldcs streaming loads ----
    const int lb = blockIdx.x;
    const int v0 = lb * 16 + warp * 2;
    const int v1 = v0 + 1;
    const bool p0 = v0 < VOCAB;
    const bool p1 = v1 < VOCAB;

    const uint4* w0 = (const uint4*)(g_wout_h + (size_t)v0 * HID);
    const uint4* w1 = (const uint4*)(g_wout_h + (size_t)v1 * HID);

    float acc0 = 0.f, acc1 = 0.f;
    #pragma unroll
    for (int it = 0; it < 8; it++) {                // 2048 halves / (32 lanes * 8) = 8
        int idx = it * 32 + lane;
        float4 ha = sh4[2 * idx];
        float4 hb = sh4[2 * idx + 1];
        if (p0) acc0 += dot8_h(__ldcs(&w0[idx]), ha, hb);
        if (p1) acc1 += dot8_h(__ldcs(&w1[idx]), ha, hb);
    }
    #pragma unroll
    for (int off = 16; off > 0; off >>= 1) {
        acc0 += __shfl_xor_sync(0xFFFFFFFFu, acc0, off);
        acc1 += __shfl_xor_sync(0xFFFFFFFFu, acc1, off);
    }
    // Plain stores: keep this step's 200 KB of logits L2-resident so the
    // refine scan in step_kernel(t+1) is L2-served.
    if (lane == 0 && p0) out[(size_t)t * VOCAB + v0] = acc0 + __ldg(&b_out[v0]);
    if (lane == 0 && p1) out[(size_t)t * VOCAB + v1] = acc1 + __ldg(&b_out[v1]);
}

extern "C" void kernel_launch(void* const* d_in, const int* in_sizes, int n_in,
                              void* d_out, int out_size)
{
    const float* emb   = (const float*)d_in[0];
    const float* W_ih  = (const float*)d_in[1];
    const float* W_hh  = (const float*)d_in[2];
    const float* b_ih  = (const float*)d_in[3];
    const float* b_hh  = (const float*)d_in[4];
    const float* W_out = (const float*)d_in[5];
    const float* b_out = (const float*)d_in[6];
    float* out = (float*)d_out;

    preamble_kernel<<<PRE_BLOCKS, 256>>>(W_out, W_hh, W_ih);

    for (int t = 0; t < T_STEPS; t++) {
        step_kernel<<<STEP_BLOCKS, 256>>>(emb, W_out, b_out, b_ih, b_hh, out, t);
        fused_logits_gh_kernel<<<FUSED_BLOCKS, 256>>>(b_out, out, t);
    }
}